// round 9
// baseline (speedup 1.0000x reference)
#include <cuda_runtime.h>
#include <cuda_bf16.h>
#include <cstdint>

// MMDLayer via mma.sync bf16 (HMMA), 2-way bf16 split (hh+hl+lh).
// out[t,s] = (1 - (||x_t||^2 + ||C_k||^2 - 2 x_t.C_k)/128)^3,  k = 511+t-s
// C[k] = init[511-k] (k<512) else x[k-512];  A row t == C[512+t].
// Kernel 1 (prep): split all 2560 C rows into bf16 hi/lo scratch + fp32 norms.
// Kernel 2 (main): 4-stage cp.async->mbarrier pipeline over k-quarters; HMMA on
//                  stage s starts as soon as its quarter lands (load/compute overlap).

#define T_LEN 2048
#define S_LEN 512
#define DIM   128
#define NROWS 2560
#define BT    32
#define BK    64
#define NKT   9
#define NTHR  256
#define PITCH 272                     // smem bytes per tile row (256B data + 16B pad)

#define ASZ    (BT * PITCH)           // 8704
#define BSZ    (BK * PITCH)           // 17408
#define OFF_AH 0
#define OFF_AL (OFF_AH + ASZ)
#define OFF_BH (OFF_AL + ASZ)
#define OFF_BL (OFF_BH + BSZ)
#define OFF_MB (OFF_BL + BSZ)         // 4 mbarriers, 8B each
#define SMEM_TOTAL (OFF_MB + 32)      // 52256 B -> 4 CTAs/SM

// ---- global scratch (device globals: allocation-free) ----
__device__ __align__(256) unsigned short g_hi[NROWS * DIM];
__device__ __align__(256) unsigned short g_lo[NROWS * DIM];
__device__ __align__(256) float          g_nrm[NROWS];

__device__ __forceinline__ uint32_t smem_u32(const void* p) {
    uint32_t a;
    asm("{ .reg .u64 t; cvta.to.shared.u64 t, %1; cvt.u32.u64 %0, t; }" : "=r"(a) : "l"(p));
    return a;
}
__device__ __forceinline__ void ldsm4(uint32_t r[4], uint32_t addr) {
    asm volatile("ldmatrix.sync.aligned.m8n8.x4.shared.b16 {%0,%1,%2,%3}, [%4];"
                 : "=r"(r[0]), "=r"(r[1]), "=r"(r[2]), "=r"(r[3]) : "r"(addr));
}
__device__ __forceinline__ void mma16816(float c[4], const uint32_t a[4],
                                         uint32_t b0, uint32_t b1) {
    asm volatile(
        "mma.sync.aligned.m16n8k16.row.col.f32.bf16.bf16.f32 "
        "{%0,%1,%2,%3}, {%4,%5,%6,%7}, {%8,%9}, {%0,%1,%2,%3};"
        : "+f"(c[0]), "+f"(c[1]), "+f"(c[2]), "+f"(c[3])
        : "r"(a[0]), "r"(a[1]), "r"(a[2]), "r"(a[3]), "r"(b0), "r"(b1));
}
__device__ __forceinline__ void cp16(uint32_t dst, const void* src) {
    asm volatile("cp.async.cg.shared.global [%0], [%1], 16;"
                 :: "r"(dst), "l"(src) : "memory");
}
__device__ __forceinline__ unsigned short us(__nv_bfloat16 h) {
    return __bfloat16_as_ushort(h);
}

#define MBAR_WAIT_P0(mbar) do {                                                  \
    asm volatile(                                                                \
        "{\n\t.reg .pred P1;\n\t"                                                \
        "WAIT_LOOP_%=:\n\t"                                                      \
        "mbarrier.try_wait.parity.acquire.cta.shared::cta.b64 P1, [%0], 0, 0x989680;\n\t" \
        "@P1 bra.uni WAIT_DONE_%=;\n\t"                                          \
        "bra.uni WAIT_LOOP_%=;\n\t"                                              \
        "WAIT_DONE_%=:\n\t}"                                                     \
        :: "r"(mbar) : "memory");                                                \
} while (0)

// ---- Kernel 1: split rows into hi/lo bf16 + norms (one warp per row) ----
__global__ __launch_bounds__(NTHR)
void prep_kernel(const float* __restrict__ x, const float* __restrict__ init)
{
    const int wid  = threadIdx.x >> 5;
    const int lane = threadIdx.x & 31;
    const int row  = blockIdx.x * 8 + wid;          // grid = 320 -> rows 0..2559

    const float* src = (row < S_LEN) ? init + (size_t)(S_LEN - 1 - row) * DIM
                                     : x    + (size_t)(row - S_LEN) * DIM;
    const float4 v = reinterpret_cast<const float4*>(src)[lane];

    __nv_bfloat16 h0 = __float2bfloat16_rn(v.x);
    __nv_bfloat16 h1 = __float2bfloat16_rn(v.y);
    __nv_bfloat16 h2 = __float2bfloat16_rn(v.z);
    __nv_bfloat16 h3 = __float2bfloat16_rn(v.w);
    __nv_bfloat16 l0 = __float2bfloat16_rn(v.x - __bfloat162float(h0));
    __nv_bfloat16 l1 = __float2bfloat16_rn(v.y - __bfloat162float(h1));
    __nv_bfloat16 l2 = __float2bfloat16_rn(v.z - __bfloat162float(h2));
    __nv_bfloat16 l3 = __float2bfloat16_rn(v.w - __bfloat162float(h3));

    uint2 H = make_uint2((uint32_t)us(h0) | ((uint32_t)us(h1) << 16),
                         (uint32_t)us(h2) | ((uint32_t)us(h3) << 16));
    uint2 L = make_uint2((uint32_t)us(l0) | ((uint32_t)us(l1) << 16),
                         (uint32_t)us(l2) | ((uint32_t)us(l3) << 16));
    reinterpret_cast<uint2*>(g_hi + (size_t)row * DIM)[lane] = H;
    reinterpret_cast<uint2*>(g_lo + (size_t)row * DIM)[lane] = L;

    float p = v.x * v.x + v.y * v.y + v.z * v.z + v.w * v.w;
    #pragma unroll
    for (int o = 16; o; o >>= 1) p += __shfl_xor_sync(0xFFFFFFFFu, p, o);
    if (lane == 0) g_nrm[row] = p;
}

// ---- Kernel 2: banded HMMA GEMM, 4-stage pipelined loads ----
__global__ __launch_bounds__(NTHR, 4)
void mmd_mma_kernel(float* __restrict__ out)
{
    extern __shared__ char sm[];
    const uint32_t smb = smem_u32(sm);
    const int tid  = threadIdx.x;
    const int wid  = tid >> 5;
    const int lane = tid & 31;
    const int bx = blockIdx.x;
    const int t0 = blockIdx.y * BT;
    const int k0 = t0 + BK * bx;

    // ---- mbarrier init (one per k-quarter stage) ----
    if (tid == 0) {
        #pragma unroll
        for (int s = 0; s < 4; s++)
            asm volatile("mbarrier.init.shared.b64 [%0], %1;"
                         :: "r"(smb + OFF_MB + 8 * s), "r"(NTHR) : "memory");
    }
    __syncthreads();

    // ---- Pipelined loads: stage s = k-cols [32s, 32s+32); 3 chunks/thread/stage ----
    // chunk id c in [0,768): c<128 A-hi, <256 A-lo, <512 B-hi, else B-lo;
    // row = (c>>2) masked, q = c&3 selects 16B within the 64B quarter.
    #pragma unroll
    for (int s = 0; s < 4; s++) {
        #pragma unroll
        for (int j = 0; j < 3; j++) {
            const int c = tid + 256 * j;
            const int q = c & 3;
            uint32_t dst;
            const unsigned short* src;
            if (c < 256) {
                const int hi  = (c < 128);
                const int row = (c >> 2) & 31;
                const unsigned short* g = hi ? g_hi : g_lo;
                src = g + (size_t)(S_LEN + t0 + row) * DIM + s * 32 + q * 8;
                dst = smb + (hi ? OFF_AH : OFF_AL)
                    + (uint32_t)(row * PITCH + s * 64 + q * 16);
            } else {
                const int hi  = (c < 512);
                const int row = (c >> 2) & 63;
                int k = k0 + row;
                if (k > NROWS - 1) k = NROWS - 1;      // clamped rows masked later
                const unsigned short* g = hi ? g_hi : g_lo;
                src = g + (size_t)k * DIM + s * 32 + q * 8;
                dst = smb + (hi ? OFF_BH : OFF_BL)
                    + (uint32_t)(row * PITCH + s * 64 + q * 16);
            }
            cp16(dst, src);
        }
        asm volatile("cp.async.mbarrier.arrive.noinc.shared::cta.b64 [%0];"
                     :: "r"(smb + OFF_MB + 8 * s) : "memory");
    }

    // ---- Prefetch epilogue norms while cp.async streams ----
    const int wm = wid & 1;
    const int wn = wid >> 1;
    const int m0 = wm * 16 + (lane >> 2);
    const int m1 = m0 + 8;
    const int ta = t0 + m0;
    const int tb = t0 + m1;
    const int nbase = wn * 16 + 2 * (lane & 3);
    const float na0 = g_nrm[S_LEN + ta];
    const float na1 = g_nrm[S_LEN + tb];
    float nb[2][2];
    #pragma unroll
    for (int nt = 0; nt < 2; nt++) {
        int kk0 = k0 + nbase + nt * 8;
        int kk1 = kk0 + 1;
        nb[nt][0] = g_nrm[kk0 > NROWS - 1 ? NROWS - 1 : kk0];
        nb[nt][1] = g_nrm[kk1 > NROWS - 1 ? NROWS - 1 : kk1];
    }

    // ---- ldmatrix addresses (16x16 warp tile; 2 warps M x 4 warps N) ----
    const int arow = wm * 16 + (lane & 7) + ((lane >> 3) & 1) * 8;
    const int acol = (lane >> 4) * 8;
    const uint32_t aH = smb + OFF_AH + (uint32_t)(arow * PITCH + acol * 2);
    const int brow = wn * 16 + (lane & 7) + (lane >> 4) * 8;
    const int bcol = ((lane >> 3) & 1) * 8;
    const uint32_t bH = smb + OFF_BH + (uint32_t)(brow * PITCH + bcol * 2);

    float acc[2][4];
    #pragma unroll
    for (int j = 0; j < 2; j++)
        #pragma unroll
        for (int q = 0; q < 4; q++)
            acc[j][q] = 0.f;

    // ---- Main loop: per stage wait its mbarrier, run 2 K-steps (hh+hl+lh) ----
    #pragma unroll
    for (int sp = 0; sp < 4; sp++) {
        MBAR_WAIT_P0(smb + OFF_MB + 8 * sp);
        #pragma unroll
        for (int kk = 0; kk < 2; kk++) {
            const uint32_t kb = (uint32_t)((sp * 2 + kk) * 32);
            uint32_t ah[4], al[4], bh[4], bl[4];
            ldsm4(ah, aH + kb);
            ldsm4(al, aH + ASZ + kb);
            ldsm4(bh, bH + kb);
            ldsm4(bl, bH + BSZ + kb);

            mma16816(acc[0], ah, bh[0], bh[1]);
            mma16816(acc[1], ah, bh[2], bh[3]);
            mma16816(acc[0], ah, bl[0], bl[1]);
            mma16816(acc[1], ah, bl[2], bl[3]);
            mma16816(acc[0], al, bh[0], bh[1]);
            mma16816(acc[1], al, bh[2], bh[3]);
        }
    }

    // ---- Epilogue: d2 = nA + nB - 2*dot; out[t, 511+t-k] = (1 - d2/128)^3 ----
    #pragma unroll
    for (int nt = 0; nt < 2; nt++) {
        const int n  = nbase + nt * 8;
        const int k  = k0 + n;
        const float* a4 = acc[nt];

        const int sa = 511 + ta - k;
        const int sb = 511 + tb - k;
        float d2, u;
        if (sa >= 0 && sa < S_LEN) {
            d2 = na0 + nb[nt][0] - 2.0f * a4[0];
            u  = 1.0f - d2 * (1.0f / 128.0f);
            out[(size_t)ta * S_LEN + sa] = u * u * u;
        }
        if ((unsigned)(sa - 1) < S_LEN) {
            d2 = na0 + nb[nt][1] - 2.0f * a4[1];
            u  = 1.0f - d2 * (1.0f / 128.0f);
            out[(size_t)ta * S_LEN + sa - 1] = u * u * u;
        }
        if (sb >= 0 && sb < S_LEN) {
            d2 = na1 + nb[nt][0] - 2.0f * a4[2];
            u  = 1.0f - d2 * (1.0f / 128.0f);
            out[(size_t)tb * S_LEN + sb] = u * u * u;
        }
        if ((unsigned)(sb - 1) < S_LEN) {
            d2 = na1 + nb[nt][1] - 2.0f * a4[3];
            u  = 1.0f - d2 * (1.0f / 128.0f);
            out[(size_t)tb * S_LEN + sb - 1] = u * u * u;
        }
    }
}

extern "C" void kernel_launch(void* const* d_in, const int* in_sizes, int n_in,
                              void* d_out, int out_size)
{
    const float* x    = (const float*)d_in[0];   // (1, 2048, 1, 128) fp32
    const float* init = (const float*)d_in[1];   // (512, 128) fp32
    float* out = (float*)d_out;                  // (1, 2048, 512) fp32

    cudaFuncSetAttribute(mmd_mma_kernel,
                         cudaFuncAttributeMaxDynamicSharedMemorySize, SMEM_TOTAL);

    prep_kernel<<<NROWS / 8, NTHR>>>(x, init);   // 320 CTAs
    dim3 grid(NKT, T_LEN / BT);                  // (9, 64) = 576 CTAs, 4/SM
    mmd_mma_kernel<<<grid, NTHR, SMEM_TOTAL>>>(out);
}

// round 10
// speedup vs baseline: 1.2143x; 1.2143x over previous
#include <cuda_runtime.h>
#include <cuda_bf16.h>
#include <cstdint>

// MMDLayer via mma.sync bf16 (HMMA), 2-way bf16 split (hh+hl+lh).
// out[t,s] = (1 - (||x_t||^2 + ||C_k||^2 - 2 x_t.C_k)/128)^3,  k = 511+t-s
// C[k] = init[511-k] (k<512) else x[k-512];  A row t == C[512+t].
// Kernel 1 (prep): split C rows into bf16 hi/lo scratch (chunk-swizzled) + norms.
// Kernel 2 (main): cp.async.bulk DMA of contiguous tiles (8 instrs/CTA instead of
//                  ~4.5K LSU ops), mbarrier completion, HMMA, epilogue.

#define T_LEN 2048
#define S_LEN 512
#define DIM   128
#define NROWS 2560
#define NROWS_PAD 2624                // pad so last k-tile bulk copies stay in-bounds
#define BT    32
#define BK    64
#define NKT   9
#define NTHR  256

// ---- smem layout (bytes); rows are 256B, NO padding (bulk copy is contiguous) ----
#define OFF_AH 0
#define OFF_AL 8192
#define OFF_BH 16384
#define OFF_BL 32768
#define OFF_NA 49152                  // 32 A norms (128B)
#define OFF_NB 49280                  // 64 B norms (256B)
#define OFF_MB 49536                  // 2 mbarriers
#define SMEM_TOTAL 49600              // -> 4 CTAs/SM

// ---- global scratch (device globals: allocation-free) ----
__device__ __align__(256) unsigned short g_hi[NROWS_PAD * DIM];
__device__ __align__(256) unsigned short g_lo[NROWS_PAD * DIM];
__device__ __align__(256) float          g_nrm[NROWS_PAD];

__device__ __forceinline__ uint32_t smem_u32(const void* p) {
    uint32_t a;
    asm("{ .reg .u64 t; cvta.to.shared.u64 t, %1; cvt.u32.u64 %0, t; }" : "=r"(a) : "l"(p));
    return a;
}
__device__ __forceinline__ void ldsm4(uint32_t r[4], uint32_t addr) {
    asm volatile("ldmatrix.sync.aligned.m8n8.x4.shared.b16 {%0,%1,%2,%3}, [%4];"
                 : "=r"(r[0]), "=r"(r[1]), "=r"(r[2]), "=r"(r[3]) : "r"(addr));
}
__device__ __forceinline__ void mma16816(float c[4], const uint32_t a[4],
                                         uint32_t b0, uint32_t b1) {
    asm volatile(
        "mma.sync.aligned.m16n8k16.row.col.f32.bf16.bf16.f32 "
        "{%0,%1,%2,%3}, {%4,%5,%6,%7}, {%8,%9}, {%0,%1,%2,%3};"
        : "+f"(c[0]), "+f"(c[1]), "+f"(c[2]), "+f"(c[3])
        : "r"(a[0]), "r"(a[1]), "r"(a[2]), "r"(a[3]), "r"(b0), "r"(b1));
}
__device__ __forceinline__ void bulk_g2s(uint32_t dst, const void* src,
                                         uint32_t bytes, uint32_t mbar) {
    asm volatile(
        "cp.async.bulk.shared::cluster.global.mbarrier::complete_tx::bytes "
        "[%0], [%1], %2, [%3];"
        :: "r"(dst), "l"(src), "r"(bytes), "r"(mbar) : "memory");
}
__device__ __forceinline__ unsigned short us(__nv_bfloat16 h) {
    return __bfloat16_as_ushort(h);
}

#define MBAR_WAIT_P0(mbar) do {                                                  \
    asm volatile(                                                                \
        "{\n\t.reg .pred P1;\n\t"                                                \
        "WAIT_LOOP_%=:\n\t"                                                      \
        "mbarrier.try_wait.parity.acquire.cta.shared::cta.b64 P1, [%0], 0, 0x989680;\n\t" \
        "@P1 bra.uni WAIT_DONE_%=;\n\t"                                          \
        "bra.uni WAIT_LOOP_%=;\n\t"                                              \
        "WAIT_DONE_%=:\n\t}"                                                     \
        :: "r"(mbar) : "memory");                                                \
} while (0)

// ---- Kernel 1: split rows into hi/lo bf16 (chunk-swizzled) + norms ----
// Swizzle: 16B chunk q of row r is stored at chunk q^(r&7) within the 256B row.
__global__ __launch_bounds__(NTHR)
void prep_kernel(const float* __restrict__ x, const float* __restrict__ init)
{
    const int wid  = threadIdx.x >> 5;
    const int lane = threadIdx.x & 31;
    const int row  = blockIdx.x * 8 + wid;          // grid = 328 -> rows 0..2623
    const int rs   = row < NROWS - 1 ? row : NROWS - 1;   // clamp source for pad rows

    const float* src = (rs < S_LEN) ? init + (size_t)(S_LEN - 1 - rs) * DIM
                                    : x    + (size_t)(rs - S_LEN) * DIM;
    const float4 v = reinterpret_cast<const float4*>(src)[lane];

    __nv_bfloat16 h0 = __float2bfloat16_rn(v.x);
    __nv_bfloat16 h1 = __float2bfloat16_rn(v.y);
    __nv_bfloat16 h2 = __float2bfloat16_rn(v.z);
    __nv_bfloat16 h3 = __float2bfloat16_rn(v.w);
    __nv_bfloat16 l0 = __float2bfloat16_rn(v.x - __bfloat162float(h0));
    __nv_bfloat16 l1 = __float2bfloat16_rn(v.y - __bfloat162float(h1));
    __nv_bfloat16 l2 = __float2bfloat16_rn(v.z - __bfloat162float(h2));
    __nv_bfloat16 l3 = __float2bfloat16_rn(v.w - __bfloat162float(h3));

    uint2 H = make_uint2((uint32_t)us(h0) | ((uint32_t)us(h1) << 16),
                         (uint32_t)us(h2) | ((uint32_t)us(h3) << 16));
    uint2 L = make_uint2((uint32_t)us(l0) | ((uint32_t)us(l1) << 16),
                         (uint32_t)us(l2) | ((uint32_t)us(l3) << 16));

    const uint32_t pchunk = (uint32_t)((lane >> 1) ^ (row & 7));
    const size_t off = (size_t)row * 256 + pchunk * 16 + (lane & 1) * 8;
    *reinterpret_cast<uint2*>(reinterpret_cast<char*>(g_hi) + off) = H;
    *reinterpret_cast<uint2*>(reinterpret_cast<char*>(g_lo) + off) = L;

    float p = v.x * v.x + v.y * v.y + v.z * v.z + v.w * v.w;
    #pragma unroll
    for (int o = 16; o; o >>= 1) p += __shfl_xor_sync(0xFFFFFFFFu, p, o);
    if (lane == 0) g_nrm[row] = p;
}

// ---- Kernel 2: banded HMMA GEMM, bulk-DMA loads ----
__global__ __launch_bounds__(NTHR, 4)
void mmd_mma_kernel(float* __restrict__ out)
{
    extern __shared__ char sm[];
    const uint32_t smb = smem_u32(sm);
    const int tid  = threadIdx.x;
    const int wid  = tid >> 5;
    const int lane = tid & 31;
    const int bx = blockIdx.x;
    const int t0 = blockIdx.y * BT;
    const int k0 = t0 + BK * bx;

    const uint32_t mb0 = smb + OFF_MB;
    const uint32_t mb1 = smb + OFF_MB + 8;

    if (tid == 0) {
        asm volatile("mbarrier.init.shared.b64 [%0], 1;" :: "r"(mb0) : "memory");
        asm volatile("mbarrier.init.shared.b64 [%0], 1;" :: "r"(mb1) : "memory");
    }
    __syncthreads();

    if (tid == 0) {
        const char* ghi = reinterpret_cast<const char*>(g_hi);
        const char* glo = reinterpret_cast<const char*>(g_lo);
        const char* gnr = reinterpret_cast<const char*>(g_nrm);
        // Stage 0: A tiles + B rows [0,32) + norms = 4*8192 + 128 + 256 = 33152 B
        asm volatile("mbarrier.arrive.expect_tx.shared.b64 _, [%0], %1;"
                     :: "r"(mb0), "r"(33152u) : "memory");
        bulk_g2s(smb + OFF_AH, ghi + (size_t)(S_LEN + t0) * 256, 8192, mb0);
        bulk_g2s(smb + OFF_AL, glo + (size_t)(S_LEN + t0) * 256, 8192, mb0);
        bulk_g2s(smb + OFF_BH, ghi + (size_t)k0 * 256,           8192, mb0);
        bulk_g2s(smb + OFF_BL, glo + (size_t)k0 * 256,           8192, mb0);
        bulk_g2s(smb + OFF_NA, gnr + (size_t)(S_LEN + t0) * 4,   128,  mb0);
        bulk_g2s(smb + OFF_NB, gnr + (size_t)k0 * 4,             256,  mb0);
        // Stage 1: B rows [32,64) = 2*8192
        asm volatile("mbarrier.arrive.expect_tx.shared.b64 _, [%0], %1;"
                     :: "r"(mb1), "r"(16384u) : "memory");
        bulk_g2s(smb + OFF_BH + 8192, ghi + (size_t)(k0 + 32) * 256, 8192, mb1);
        bulk_g2s(smb + OFF_BL + 8192, glo + (size_t)(k0 + 32) * 256, 8192, mb1);
    }

    // ---- Warp tiling: 2 warps M (16 rows) x 4 warps N (16 cols) ----
    const int wm = wid & 1;
    const int wn = wid >> 1;
    const int m0 = wm * 16 + (lane >> 2);
    const int m1 = m0 + 8;
    const int ta = t0 + m0;
    const int tb = t0 + m1;
    const int nbase = wn * 16 + 2 * (lane & 3);

    // ldmatrix addressing with chunk swizzle: chunk(ks) = qbase + 2*ks, phys = ^ (row&7)
    const int arow = wm * 16 + (lane & 7) + ((lane >> 3) & 1) * 8;
    const int qa0  = lane >> 4;                    // 0/1 (col 0 / col 8)
    const int rxa  = arow & 7;
    const uint32_t aBase = smb + OFF_AH + (uint32_t)(arow * 256);
    const int brow = wn * 16 + (lane & 7) + (lane >> 4) * 8;
    const int qb0  = (lane >> 3) & 1;
    const int rxb  = brow & 7;
    const uint32_t bBase = smb + OFF_BH + (uint32_t)(brow * 256);

    float acc[2][4];
    #pragma unroll
    for (int j = 0; j < 2; j++)
        #pragma unroll
        for (int q = 0; q < 4; q++)
            acc[j][q] = 0.f;

    // Warps with wn>=2 read B rows [32,64) -> also need stage 1.
    MBAR_WAIT_P0(mb0);
    if (wn >= 2) MBAR_WAIT_P0(mb1);

    // ---- Norms from smem ----
    const float* sNA = (const float*)(sm + OFF_NA);
    const float* sNB = (const float*)(sm + OFF_NB);
    const float na0 = sNA[m0];
    const float na1 = sNA[m1];
    float nb[2][2];
    #pragma unroll
    for (int nt = 0; nt < 2; nt++) {
        nb[nt][0] = sNB[nbase + nt * 8];
        nb[nt][1] = sNB[nbase + nt * 8 + 1];
    }

    // ---- Main loop: 8 K-steps of 16; hh + hl + lh ----
    #pragma unroll
    for (int ks = 0; ks < 8; ks++) {
        const uint32_t qa = (uint32_t)(((qa0 + 2 * ks) ^ rxa) << 4);
        const uint32_t qb = (uint32_t)(((qb0 + 2 * ks) ^ rxb) << 4);
        uint32_t ah[4], al[4], bh[4], bl[4];
        ldsm4(ah, aBase + qa);
        ldsm4(al, aBase + (OFF_AL - OFF_AH) + qa);
        ldsm4(bh, bBase + qb);
        ldsm4(bl, bBase + (OFF_BL - OFF_BH) + qb);

        mma16816(acc[0], ah, bh[0], bh[1]);
        mma16816(acc[1], ah, bh[2], bh[3]);
        mma16816(acc[0], ah, bl[0], bl[1]);
        mma16816(acc[1], ah, bl[2], bl[3]);
        mma16816(acc[0], al, bh[0], bh[1]);
        mma16816(acc[1], al, bh[2], bh[3]);
    }

    // ---- Epilogue: d2 = nA + nB - 2*dot; out[t, 511+t-k] = (1 - d2/128)^3 ----
    #pragma unroll
    for (int nt = 0; nt < 2; nt++) {
        const int n  = nbase + nt * 8;
        const int k  = k0 + n;
        const float* a4 = acc[nt];

        const int sa = 511 + ta - k;
        const int sb = 511 + tb - k;
        float d2, u;
        if (sa >= 0 && sa < S_LEN) {
            d2 = na0 + nb[nt][0] - 2.0f * a4[0];
            u  = 1.0f - d2 * (1.0f / 128.0f);
            out[(size_t)ta * S_LEN + sa] = u * u * u;
        }
        if ((unsigned)(sa - 1) < S_LEN) {
            d2 = na0 + nb[nt][1] - 2.0f * a4[1];
            u  = 1.0f - d2 * (1.0f / 128.0f);
            out[(size_t)ta * S_LEN + sa - 1] = u * u * u;
        }
        if (sb >= 0 && sb < S_LEN) {
            d2 = na1 + nb[nt][0] - 2.0f * a4[2];
            u  = 1.0f - d2 * (1.0f / 128.0f);
            out[(size_t)tb * S_LEN + sb] = u * u * u;
        }
        if ((unsigned)(sb - 1) < S_LEN) {
            d2 = na1 + nb[nt][1] - 2.0f * a4[3];
            u  = 1.0f - d2 * (1.0f / 128.0f);
            out[(size_t)tb * S_LEN + sb - 1] = u * u * u;
        }
    }
}

extern "C" void kernel_launch(void* const* d_in, const int* in_sizes, int n_in,
                              void* d_out, int out_size)
{
    const float* x    = (const float*)d_in[0];   // (1, 2048, 1, 128) fp32
    const float* init = (const float*)d_in[1];   // (512, 128) fp32
    float* out = (float*)d_out;                  // (1, 2048, 512) fp32

    cudaFuncSetAttribute(mmd_mma_kernel,
                         cudaFuncAttributeMaxDynamicSharedMemorySize, SMEM_TOTAL);

    prep_kernel<<<NROWS_PAD / 8, NTHR>>>(x, init);   // 328 CTAs
    dim3 grid(NKT, T_LEN / BT);                      // (9, 64) = 576 CTAs, 4/SM
    mmd_mma_kernel<<<grid, NTHR, SMEM_TOTAL>>>(out);
}

// round 11
// speedup vs baseline: 1.2179x; 1.0030x over previous
#include <cuda_runtime.h>
#include <cuda_bf16.h>
#include <cstdint>

// MMDLayer via mma.sync bf16 (HMMA), 2-way bf16 split (hh+hl+lh).
// out[t,s] = (1 - (||x_t||^2 + ||C_k||^2 - 2 x_t.C_k)/128)^3,  k = 511+t-s
// C[k] = init[511-k] (k<512) else x[k-512];  A row t == C[512+t].
// Kernel 1 (prep): split C rows into interleaved hi/lo bf16 scratch (512B/row,
//                  chunk-swizzled) + fp32 norms; PDL launch_dependents at end.
// Kernel 2 (main): PDL wait; bulk-DMA A (32KB) + B in two 16KB stages (mbarriers);
//                  64x64 tile/CTA, 8 warps with 32x16 warp tiles; HMMA; epilogue.

#define T_LEN 2048
#define S_LEN 512
#define DIM   128
#define NROWS 2560
#define NROWS_PAD 2624
#define BT    64
#define BK    64
#define NKT   9
#define NTHR  256

// ---- smem layout (bytes) ----
#define OFF_A  0                      // 64 rows x 512B (hi@+0, lo@+256) = 32768
#define OFF_B0 32768                  // B rows [0,32):  32 x 512 = 16384
#define OFF_B1 49152                  // B rows [32,64): 16384
#define OFF_NA 65536                  // 64 A norms (256B)
#define OFF_NB 65792                  // 64 B norms (256B)
#define OFF_MB 66048                  // 2 mbarriers
#define SMEM_TOTAL 66080

// ---- global scratch (device globals: allocation-free) ----
__device__ __align__(256) unsigned char g_c[NROWS_PAD * 512];   // hi|lo interleaved
__device__ __align__(256) float         g_nrm[NROWS_PAD];

__device__ __forceinline__ uint32_t smem_u32(const void* p) {
    uint32_t a;
    asm("{ .reg .u64 t; cvta.to.shared.u64 t, %1; cvt.u32.u64 %0, t; }" : "=r"(a) : "l"(p));
    return a;
}
__device__ __forceinline__ void ldsm4(uint32_t r[4], uint32_t addr) {
    asm volatile("ldmatrix.sync.aligned.m8n8.x4.shared.b16 {%0,%1,%2,%3}, [%4];"
                 : "=r"(r[0]), "=r"(r[1]), "=r"(r[2]), "=r"(r[3]) : "r"(addr));
}
__device__ __forceinline__ void mma16816(float c[4], const uint32_t a[4],
                                         uint32_t b0, uint32_t b1) {
    asm volatile(
        "mma.sync.aligned.m16n8k16.row.col.f32.bf16.bf16.f32 "
        "{%0,%1,%2,%3}, {%4,%5,%6,%7}, {%8,%9}, {%0,%1,%2,%3};"
        : "+f"(c[0]), "+f"(c[1]), "+f"(c[2]), "+f"(c[3])
        : "r"(a[0]), "r"(a[1]), "r"(a[2]), "r"(a[3]), "r"(b0), "r"(b1));
}
__device__ __forceinline__ void bulk_g2s(uint32_t dst, const void* src,
                                         uint32_t bytes, uint32_t mbar) {
    asm volatile(
        "cp.async.bulk.shared::cluster.global.mbarrier::complete_tx::bytes "
        "[%0], [%1], %2, [%3];"
        :: "r"(dst), "l"(src), "r"(bytes), "r"(mbar) : "memory");
}
__device__ __forceinline__ unsigned short us(__nv_bfloat16 h) {
    return __bfloat16_as_ushort(h);
}

#define MBAR_WAIT_P0(mbar) do {                                                  \
    asm volatile(                                                                \
        "{\n\t.reg .pred P1;\n\t"                                                \
        "WAIT_LOOP_%=:\n\t"                                                      \
        "mbarrier.try_wait.parity.acquire.cta.shared::cta.b64 P1, [%0], 0, 0x989680;\n\t" \
        "@P1 bra.uni WAIT_DONE_%=;\n\t"                                          \
        "bra.uni WAIT_LOOP_%=;\n\t"                                              \
        "WAIT_DONE_%=:\n\t}"                                                     \
        :: "r"(mbar) : "memory");                                                \
} while (0)

// ---- Kernel 1: split rows into interleaved hi/lo bf16 (chunk-swizzled) + norms ----
// Within each 256B half: 16B chunk q of row r stored at chunk q^(r&7).
__global__ __launch_bounds__(NTHR)
void prep_kernel(const float* __restrict__ x, const float* __restrict__ init)
{
    const int wid  = threadIdx.x >> 5;
    const int lane = threadIdx.x & 31;
    const int row  = blockIdx.x * 8 + wid;          // grid = 328 -> rows 0..2623
    const int rs   = row < NROWS - 1 ? row : NROWS - 1;

    const float* src = (rs < S_LEN) ? init + (size_t)(S_LEN - 1 - rs) * DIM
                                    : x    + (size_t)(rs - S_LEN) * DIM;
    const float4 v = reinterpret_cast<const float4*>(src)[lane];

    __nv_bfloat16 h0 = __float2bfloat16_rn(v.x);
    __nv_bfloat16 h1 = __float2bfloat16_rn(v.y);
    __nv_bfloat16 h2 = __float2bfloat16_rn(v.z);
    __nv_bfloat16 h3 = __float2bfloat16_rn(v.w);
    __nv_bfloat16 l0 = __float2bfloat16_rn(v.x - __bfloat162float(h0));
    __nv_bfloat16 l1 = __float2bfloat16_rn(v.y - __bfloat162float(h1));
    __nv_bfloat16 l2 = __float2bfloat16_rn(v.z - __bfloat162float(h2));
    __nv_bfloat16 l3 = __float2bfloat16_rn(v.w - __bfloat162float(h3));

    uint2 H = make_uint2((uint32_t)us(h0) | ((uint32_t)us(h1) << 16),
                         (uint32_t)us(h2) | ((uint32_t)us(h3) << 16));
    uint2 L = make_uint2((uint32_t)us(l0) | ((uint32_t)us(l1) << 16),
                         (uint32_t)us(l2) | ((uint32_t)us(l3) << 16));

    const uint32_t pchunk = (uint32_t)((lane >> 1) ^ (row & 7));
    const size_t base = (size_t)row * 512 + pchunk * 16 + (lane & 1) * 8;
    *reinterpret_cast<uint2*>(g_c + base)       = H;   // hi half
    *reinterpret_cast<uint2*>(g_c + base + 256) = L;   // lo half

    float p = v.x * v.x + v.y * v.y + v.z * v.z + v.w * v.w;
    #pragma unroll
    for (int o = 16; o; o >>= 1) p += __shfl_xor_sync(0xFFFFFFFFu, p, o);
    if (lane == 0) g_nrm[row] = p;

    // PDL: allow dependent (main) kernel to launch; prior stores become visible
    // to it after its griddepcontrol.wait.
    asm volatile("griddepcontrol.launch_dependents;" ::: "memory");
}

// ---- Kernel 2: banded HMMA GEMM, bulk-DMA loads, 64x64 tile ----
__global__ __launch_bounds__(NTHR, 2)
void mmd_mma_kernel(float* __restrict__ out)
{
    extern __shared__ char sm[];
    const uint32_t smb = smem_u32(sm);
    const int tid  = threadIdx.x;
    const int wid  = tid >> 5;
    const int lane = tid & 31;
    const int bx = blockIdx.x;
    const int t0 = blockIdx.y * BT;
    const int k0 = t0 + BK * bx;

    const uint32_t mb0 = smb + OFF_MB;
    const uint32_t mb1 = smb + OFF_MB + 8;

    if (tid == 0) {
        asm volatile("mbarrier.init.shared.b64 [%0], 1;" :: "r"(mb0) : "memory");
        asm volatile("mbarrier.init.shared.b64 [%0], 1;" :: "r"(mb1) : "memory");
    }
    __syncthreads();

    if (tid == 0) {
        // PDL: wait for prep kernel's writes to be visible.
        asm volatile("griddepcontrol.wait;" ::: "memory");
        const unsigned char* gc = g_c;
        const char* gnr = reinterpret_cast<const char*>(g_nrm);
        // Stage 0: A (32KB) + B rows [0,32) (16KB) + both norm blocks (512B)
        asm volatile("mbarrier.arrive.expect_tx.shared.b64 _, [%0], %1;"
                     :: "r"(mb0), "r"(49664u) : "memory");
        bulk_g2s(smb + OFF_A,  gc + (size_t)(S_LEN + t0) * 512, 32768, mb0);
        bulk_g2s(smb + OFF_B0, gc + (size_t)k0 * 512,           16384, mb0);
        bulk_g2s(smb + OFF_NA, gnr + (size_t)(S_LEN + t0) * 4,  256,   mb0);
        bulk_g2s(smb + OFF_NB, gnr + (size_t)k0 * 4,            256,   mb0);
        // Stage 1: B rows [32,64)
        asm volatile("mbarrier.arrive.expect_tx.shared.b64 _, [%0], %1;"
                     :: "r"(mb1), "r"(16384u) : "memory");
        bulk_g2s(smb + OFF_B1, gc + (size_t)(k0 + 32) * 512, 16384, mb1);
    }

    // ---- Warp tiling: 2 warps M (32 rows each) x 4 warps N (16 cols each) ----
    const int wm = wid & 1;
    const int wn = wid >> 1;

    // A fragment addressing (two m16 tiles at +0 and +16 rows)
    const int arow = wm * 32 + (lane & 7) + ((lane >> 3) & 1) * 8;
    const int qa0  = lane >> 4;                 // col 0 / col 8 within k-step
    const int rxa  = arow & 7;                  // same for arow+16
    const uint32_t aB0 = smb + OFF_A + (uint32_t)(arow * 512);
    const uint32_t aB1 = aB0 + 16 * 512;
    // B fragment addressing (stage buffer selected by wn)
    const int brow = wn * 16 + (lane & 7) + (lane >> 4) * 8;   // 0..63
    const int qb0  = (lane >> 3) & 1;
    const int rxb  = brow & 7;
    const uint32_t bB = smb + (brow < 32 ? OFF_B0 : OFF_B1)
                      + (uint32_t)((brow & 31) * 512);

    float acc[2][2][4];
    #pragma unroll
    for (int i = 0; i < 2; i++)
        #pragma unroll
        for (int j = 0; j < 2; j++)
            #pragma unroll
            for (int q = 0; q < 4; q++)
                acc[i][j][q] = 0.f;

    MBAR_WAIT_P0(mb0);
    if (wn >= 2) MBAR_WAIT_P0(mb1);

    // ---- Norms from smem ----
    const float* sNA = (const float*)(sm + OFF_NA);
    const float* sNB = (const float*)(sm + OFF_NB);
    const int nbase = wn * 16 + 2 * (lane & 3);
    float nb[2][2];
    #pragma unroll
    for (int nt = 0; nt < 2; nt++) {
        nb[nt][0] = sNB[nbase + nt * 8];
        nb[nt][1] = sNB[nbase + nt * 8 + 1];
    }

    // ---- Main loop: 8 K-steps of 16; hh + hl + lh ----
    #pragma unroll
    for (int ks = 0; ks < 8; ks++) {
        const uint32_t qa = (uint32_t)(((qa0 + 2 * ks) ^ rxa) << 4);
        const uint32_t qb = (uint32_t)(((qb0 + 2 * ks) ^ rxb) << 4);
        uint32_t ah0[4], ah1[4], al0[4], al1[4], bh[4], bl[4];
        ldsm4(ah0, aB0 + qa);
        ldsm4(ah1, aB1 + qa);
        ldsm4(al0, aB0 + 256 + qa);
        ldsm4(al1, aB1 + 256 + qa);
        ldsm4(bh,  bB + qb);
        ldsm4(bl,  bB + 256 + qb);

        mma16816(acc[0][0], ah0, bh[0], bh[1]);   // hh
        mma16816(acc[0][1], ah0, bh[2], bh[3]);
        mma16816(acc[1][0], ah1, bh[0], bh[1]);
        mma16816(acc[1][1], ah1, bh[2], bh[3]);
        mma16816(acc[0][0], ah0, bl[0], bl[1]);   // hl
        mma16816(acc[0][1], ah0, bl[2], bl[3]);
        mma16816(acc[1][0], ah1, bl[0], bl[1]);
        mma16816(acc[1][1], ah1, bl[2], bl[3]);
        mma16816(acc[0][0], al0, bh[0], bh[1]);   // lh
        mma16816(acc[0][1], al0, bh[2], bh[3]);
        mma16816(acc[1][0], al1, bh[0], bh[1]);
        mma16816(acc[1][1], al1, bh[2], bh[3]);
    }

    // ---- Epilogue: d2 = nA + nB - 2*dot; out[t, 511+t-k] = (1 - d2/128)^3 ----
    #pragma unroll
    for (int mt = 0; mt < 2; mt++) {
        const int m  = wm * 32 + mt * 16 + (lane >> 2);
        const float na0 = sNA[m];
        const float na1 = sNA[m + 8];
        const int ta = t0 + m;
        const int tb = ta + 8;
        #pragma unroll
        for (int nt = 0; nt < 2; nt++) {
            const int n  = nbase + nt * 8;
            const int k  = k0 + n;
            const float* a4 = acc[mt][nt];

            const int sa = 511 + ta - k;
            const int sb = 511 + tb - k;
            float d2, u;
            if (sa >= 0 && sa < S_LEN) {
                d2 = na0 + nb[nt][0] - 2.0f * a4[0];
                u  = 1.0f - d2 * (1.0f / 128.0f);
                out[(size_t)ta * S_LEN + sa] = u * u * u;
            }
            if ((unsigned)(sa - 1) < S_LEN) {
                d2 = na0 + nb[nt][1] - 2.0f * a4[1];
                u  = 1.0f - d2 * (1.0f / 128.0f);
                out[(size_t)ta * S_LEN + sa - 1] = u * u * u;
            }
            if (sb >= 0 && sb < S_LEN) {
                d2 = na1 + nb[nt][0] - 2.0f * a4[2];
                u  = 1.0f - d2 * (1.0f / 128.0f);
                out[(size_t)tb * S_LEN + sb] = u * u * u;
            }
            if ((unsigned)(sb - 1) < S_LEN) {
                d2 = na1 + nb[nt][1] - 2.0f * a4[3];
                u  = 1.0f - d2 * (1.0f / 128.0f);
                out[(size_t)tb * S_LEN + sb - 1] = u * u * u;
            }
        }
    }
}

extern "C" void kernel_launch(void* const* d_in, const int* in_sizes, int n_in,
                              void* d_out, int out_size)
{
    const float* x    = (const float*)d_in[0];   // (1, 2048, 1, 128) fp32
    const float* init = (const float*)d_in[1];   // (512, 128) fp32
    float* out = (float*)d_out;                  // (1, 2048, 512) fp32

    cudaFuncSetAttribute(mmd_mma_kernel,
                         cudaFuncAttributeMaxDynamicSharedMemorySize, SMEM_TOTAL);

    prep_kernel<<<NROWS_PAD / 8, NTHR>>>(x, init);   // 328 CTAs

    // Main kernel with PDL (programmatic stream serialization)
    cudaLaunchConfig_t cfg = {};
    cfg.gridDim  = dim3(NKT, T_LEN / BT, 1);         // (9, 32) = 288 CTAs
    cfg.blockDim = dim3(NTHR, 1, 1);
    cfg.dynamicSmemBytes = SMEM_TOTAL;
    cudaLaunchAttribute attr[1];
    attr[0].id = cudaLaunchAttributeProgrammaticStreamSerialization;
    attr[0].val.programmaticStreamSerializationAllowed = 1;
    cfg.attrs = attr;
    cfg.numAttrs = 1;
    cudaLaunchKernelEx(&cfg, mmd_mma_kernel, out);
}